// round 13
// baseline (speedup 1.0000x reference)
#include <cuda_runtime.h>

// BiasedFeatureDropout: out = x * 1.25 * (threefry_bits(i) < T(channel))
// Bit-exact JAX partitionable threefry-2x32, keys (0,1), counter hi=0.
//
// Round-13 build: R12 (best, 134.4us; all adds on IMAD via opaque 'one')
// + exactly 4 rotates offloaded to the fma pipe as plain-C++ wide-muls
// (IMAD.WIDE = 2 fma slots; LOP3 fuses (lo|hi)^x0 on alu).
// Budget: alu 43 -> 39 slots/elem (binding), fma 30 -> 38. Both pipes
// ~balanced at ~78 cyc vs R12's 86.

static constexpr unsigned KS2      = 0x1BD11BDBu;   // 0 ^ 1 ^ 0x1BD11BDA
static constexpr unsigned HW       = 56u * 56u;     // 3136, divisible by 8
static constexpr unsigned THR_BIAS = 858993664u;    // keep=0.2f
static constexpr unsigned THR_REG  = 3435974144u;   // keep=0.8f

// a*one + c -> IMAD (fma pipe); 'one' is a runtime kernel arg (==1)
__device__ __forceinline__ unsigned madd(unsigned a, unsigned one, unsigned c) {
    unsigned r;
    asm("mad.lo.u32 %0, %1, %2, %3;" : "=r"(r) : "r"(a), "r"(one), "r"(c));
    return r;
}

// SHF round: IMAD add (fma) + SHF rotate (alu) + LOP3 xor (alu)
#define RS(rr)      { x0 = madd(x1, one, x0);                      \
                      x1 = __funnelshift_l(x1, x1, (rr)) ^ x0; }
// SHF round with x0 key-injection as a second IMAD (fma)
#define RSJ(rr, a)  { x0 = madd(x1, one, x0); x0 = madd(x0, one, (a)); \
                      x1 = __funnelshift_l(x1, x1, (rr)) ^ x0; }
// PRMT round: rot16 sel=0x1032, rot24 sel=0x0321
#define RP(sel)     { x0 = madd(x1, one, x0);                      \
                      x1 = __byte_perm(x1, 0u, (sel)) ^ x0; }
// WIDE round: IMAD add (fma) + IMAD.WIDE rotate (fma, 2 slots)
//             + single LOP3 (lo|hi)^x0 (alu)
#define RW(pp)      { x0 = madd(x1, one, x0);                              \
                      unsigned long long t_ = (unsigned long long)x1 * (pp); \
                      x1 = ((unsigned)t_ | (unsigned)(t_ >> 32)) ^ x0; }

__device__ __forceinline__ unsigned threefry_bits(unsigned base, unsigned i,
                                                  unsigned one,
                                                  unsigned p15, unsigned p29) {
    unsigned x0, x1;
    x1 = madd(base, one, i + 1u);                // x1 = ctr + ks1(=1)
    // r1 (rot13): x0 = 0 + x1 (register alias), x1 = rot13(x1) ^ x0
    x0 = x1;
    x1 = __funnelshift_l(x1, x1, 13) ^ x0;
    RW(p15)                                      // r2   wide rot15
    RS(26) RS(6)                                 // r3-r4
    x1 = madd(x1, one, KS2 + 1u);                // inj1: x1 += ks2+1
    RSJ(17, 1u)                                  // r5  (x0 += ks1=1, IMAD)
    RW(p29)                                      // r6   wide rot29
    RP(0x1032u)                                  // r7  rot16
    RP(0x0321u)                                  // r8  rot24
    x1 = madd(x1, one, 2u);                      // inj2: x1 += ks0+2
    RSJ(13, KS2)                                 // r9  (x0 += ks2, IMAD)
    RW(p15)                                      // r10  wide rot15
    RS(26) RS(6)                                 // r11-r12
    x1 = madd(x1, one, 4u);                      // inj3: x1 += ks1+3
    RS(17)                                       // r13 (x0 += ks0=0, free)
    RS(29)                                       // r14
    RP(0x1032u)                                  // r15 rot16
    RP(0x0321u)                                  // r16 rot24
    x1 = madd(x1, one, KS2 + 4u);                // inj4: x1 += ks2+4
    RSJ(13, 1u)                                  // r17 (x0 += ks1=1, IMAD)
    RW(p15)                                      // r18  wide rot15
    RS(26) RS(6)                                 // r19-r20
    // final: (x0 + ks2) ^ (x1 + ks0 + 5) — both adds on IMAD
    return madd(x0, one, KS2) ^ madd(x1, one, 5u);
}

__global__ __launch_bounds__(256, 4)
void biased_dropout_kernel(const float4* __restrict__ x,
                           float4* __restrict__ y,
                           unsigned one) {          // always 1, opaque to ptxas
    unsigned t = blockIdx.x * blockDim.x + threadIdx.x;   // grid covers n exactly

    unsigned base = t * 8u;
    unsigned ch  = (base / HW) & 255u;               // HW % 8 == 0
    unsigned thr = (ch < 32u) ? THR_BIAS : THR_REG;

    unsigned p15 = one << 15, p29 = one << 29;       // runtime-opaque pow2s

    float4 v0 = x[2u * t];
    float4 v1 = x[2u * t + 1u];

    unsigned b[8];
#pragma unroll
    for (int i = 0; i < 8; i++)
        b[i] = threefry_bits(base, (unsigned)i, one, p15, p29);

    float4 o0, o1;
    o0.x = (b[0] < thr) ? v0.x * 1.25f : 0.0f;
    o0.y = (b[1] < thr) ? v0.y * 1.25f : 0.0f;
    o0.z = (b[2] < thr) ? v0.z * 1.25f : 0.0f;
    o0.w = (b[3] < thr) ? v0.w * 1.25f : 0.0f;
    o1.x = (b[4] < thr) ? v1.x * 1.25f : 0.0f;
    o1.y = (b[5] < thr) ? v1.y * 1.25f : 0.0f;
    o1.z = (b[6] < thr) ? v1.z * 1.25f : 0.0f;
    o1.w = (b[7] < thr) ? v1.w * 1.25f : 0.0f;

    y[2u * t]      = o0;
    y[2u * t + 1u] = o1;
}

extern "C" void kernel_launch(void* const* d_in, const int* in_sizes, int n_in,
                              void* d_out, int out_size) {
    (void)n_in; (void)out_size;
    const float4* x = (const float4*)d_in[0];
    float4* y = (float4*)d_out;
    unsigned n = (unsigned)in_sizes[0];          // 51,380,224
    unsigned n_thr = n / 8u;                     // 6,422,528 (exact)
    unsigned blocks = n_thr / 256u;              // 25,088 (exact, no remainder)
    biased_dropout_kernel<<<blocks, 256>>>(x, y, 1u);
}

// round 14
// speedup vs baseline: 1.0109x; 1.0109x over previous
#include <cuda_runtime.h>

// BiasedFeatureDropout: out = x * 1.25 * (threefry_bits(i) < T(channel))
// Bit-exact JAX partitionable threefry-2x32, keys (0,1), counter hi=0.
//
// Round-14 build: R13's balanced pipe mix (4 wide rotates on the fma pipe,
// all adds on IMAD) at R12's occupancy. Key change: 4 elems/thread
// + __launch_bounds__(256, 8) pins regs at 32 -> full occupancy, so the
// wide rounds' latency stays hidden (R13's regs=40/occ=68% failure mode).
// Budget: alu ~38, fma ~38 slots/elem, balanced at ~76 cyc vs R12's 86.

static constexpr unsigned KS2      = 0x1BD11BDBu;   // 0 ^ 1 ^ 0x1BD11BDA
static constexpr unsigned HW       = 56u * 56u;     // 3136, divisible by 4
static constexpr unsigned THR_BIAS = 858993664u;    // keep=0.2f
static constexpr unsigned THR_REG  = 3435974144u;   // keep=0.8f

// a*one + c -> IMAD (fma pipe); 'one' is a runtime kernel arg (==1)
__device__ __forceinline__ unsigned madd(unsigned a, unsigned one, unsigned c) {
    unsigned r;
    asm("mad.lo.u32 %0, %1, %2, %3;" : "=r"(r) : "r"(a), "r"(one), "r"(c));
    return r;
}

// SHF round: IMAD add (fma) + SHF rotate (alu) + LOP3 xor (alu)
#define RS(rr)      { x0 = madd(x1, one, x0);                      \
                      x1 = __funnelshift_l(x1, x1, (rr)) ^ x0; }
// SHF round with x0 key-injection as a second IMAD (fma)
#define RSJ(rr, a)  { x0 = madd(x1, one, x0); x0 = madd(x0, one, (a)); \
                      x1 = __funnelshift_l(x1, x1, (rr)) ^ x0; }
// PRMT round: rot16 sel=0x1032, rot24 sel=0x0321
#define RP(sel)     { x0 = madd(x1, one, x0);                      \
                      x1 = __byte_perm(x1, 0u, (sel)) ^ x0; }
// WIDE round: IMAD add (fma) + IMAD.WIDE rotate (fma, 2 slots)
//             + single LOP3 (lo|hi)^x0 (alu)
#define RW(pp)      { x0 = madd(x1, one, x0);                              \
                      unsigned long long t_ = (unsigned long long)x1 * (pp); \
                      x1 = ((unsigned)t_ | (unsigned)(t_ >> 32)) ^ x0; }

__device__ __forceinline__ unsigned threefry_bits(unsigned base, unsigned i,
                                                  unsigned one,
                                                  unsigned p15, unsigned p29) {
    unsigned x0, x1;
    x1 = madd(base, one, i + 1u);                // x1 = ctr + ks1(=1)
    // r1 (rot13): x0 = 0 + x1 (register alias), x1 = rot13(x1) ^ x0
    x0 = x1;
    x1 = __funnelshift_l(x1, x1, 13) ^ x0;
    RW(p15)                                      // r2   wide rot15
    RS(26) RS(6)                                 // r3-r4
    x1 = madd(x1, one, KS2 + 1u);                // inj1: x1 += ks2+1
    RSJ(17, 1u)                                  // r5  (x0 += ks1=1, IMAD)
    RW(p29)                                      // r6   wide rot29
    RP(0x1032u)                                  // r7  rot16
    RP(0x0321u)                                  // r8  rot24
    x1 = madd(x1, one, 2u);                      // inj2: x1 += ks0+2
    RSJ(13, KS2)                                 // r9  (x0 += ks2, IMAD)
    RW(p15)                                      // r10  wide rot15
    RS(26) RS(6)                                 // r11-r12
    x1 = madd(x1, one, 4u);                      // inj3: x1 += ks1+3
    RS(17)                                       // r13 (x0 += ks0=0, free)
    RS(29)                                       // r14
    RP(0x1032u)                                  // r15 rot16
    RP(0x0321u)                                  // r16 rot24
    x1 = madd(x1, one, KS2 + 4u);                // inj4: x1 += ks2+4
    RSJ(13, 1u)                                  // r17 (x0 += ks1=1, IMAD)
    RW(p15)                                      // r18  wide rot15
    RS(26) RS(6)                                 // r19-r20
    // final: (x0 + ks2) ^ (x1 + ks0 + 5) — both adds on IMAD
    return madd(x0, one, KS2) ^ madd(x1, one, 5u);
}

__global__ __launch_bounds__(256, 8)   // pin 32 regs -> full occupancy
void biased_dropout_kernel(const float4* __restrict__ x,
                           float4* __restrict__ y,
                           unsigned one) {          // always 1, opaque to ptxas
    unsigned t = blockIdx.x * blockDim.x + threadIdx.x;   // grid covers n exactly

    unsigned base = t * 4u;
    unsigned ch  = (base / HW) & 255u;               // HW % 4 == 0
    unsigned thr = (ch < 32u) ? THR_BIAS : THR_REG;

    unsigned p15 = one << 15, p29 = one << 29;       // runtime-opaque pow2s

    float4 v = x[t];

    unsigned b0 = threefry_bits(base, 0u, one, p15, p29);
    unsigned b1 = threefry_bits(base, 1u, one, p15, p29);
    unsigned b2 = threefry_bits(base, 2u, one, p15, p29);
    unsigned b3 = threefry_bits(base, 3u, one, p15, p29);

    float4 o;
    o.x = (b0 < thr) ? v.x * 1.25f : 0.0f;
    o.y = (b1 < thr) ? v.y * 1.25f : 0.0f;
    o.z = (b2 < thr) ? v.z * 1.25f : 0.0f;
    o.w = (b3 < thr) ? v.w * 1.25f : 0.0f;

    y[t] = o;
}

extern "C" void kernel_launch(void* const* d_in, const int* in_sizes, int n_in,
                              void* d_out, int out_size) {
    (void)n_in; (void)out_size;
    const float4* x = (const float4*)d_in[0];
    float4* y = (float4*)d_out;
    unsigned n = (unsigned)in_sizes[0];          // 51,380,224
    unsigned n_vec = n / 4u;                     // 12,845,056 (exact)
    unsigned blocks = n_vec / 256u;              // 50,176 (exact, no remainder)
    biased_dropout_kernel<<<blocks, 256>>>(x, y, 1u);
}

// round 15
// speedup vs baseline: 1.0121x; 1.0012x over previous
#include <cuda_runtime.h>

// BiasedFeatureDropout: out = x * 1.25 * (threefry_bits(i) < T(channel))
// Bit-exact JAX partitionable threefry-2x32, keys (0,1), counter hi=0.
//
// Round-15 build: identical instruction *mix* to R12 (best, 134.4us) but
// every forced-IMAD add is plain C++ `a * one + c` (one = runtime 1)
// instead of an asm mad.lo block. Same IMAD in SASS, but ptxas keeps
// full register-allocation freedom -> removes the constraint-induced
// MOVs that inflated R12 from ~75 static to 79.3 issued instrs/elem.
// Model: issue-limited at 0.82 instr/cyc; dur scales with total instrs.

static constexpr unsigned KS2      = 0x1BD11BDBu;   // 0 ^ 1 ^ 0x1BD11BDA
static constexpr unsigned HW       = 56u * 56u;     // 3136, divisible by 8
static constexpr unsigned THR_BIAS = 858993664u;    // keep=0.2f
static constexpr unsigned THR_REG  = 3435974144u;   // keep=0.8f

// SHF round: IMAD add (fma) + SHF rotate (alu) + LOP3 xor (alu)
#define RS(rr)      { x0 = x1 * one + x0;                          \
                      x1 = __funnelshift_l(x1, x1, (rr)) ^ x0; }
// SHF round with x0 key-injection as a second IMAD (fma)
#define RSJ(rr, a)  { x0 = x1 * one + x0; x0 = x0 * one + (a);     \
                      x1 = __funnelshift_l(x1, x1, (rr)) ^ x0; }
// PRMT round: rot16 sel=0x1032, rot24 sel=0x0321
#define RP(sel)     { x0 = x1 * one + x0;                          \
                      x1 = __byte_perm(x1, 0u, (sel)) ^ x0; }

__device__ __forceinline__ unsigned threefry_bits(unsigned base, unsigned i,
                                                  unsigned one) {
    unsigned x0, x1;
    x1 = base * one + (i + 1u);                  // x1 = ctr + ks1(=1), IMAD
    // r1 (rot13): x0 = 0 + x1 (register alias), x1 = rot13(x1) ^ x0
    x0 = x1;
    x1 = __funnelshift_l(x1, x1, 13) ^ x0;
    RS(15) RS(26) RS(6)                          // r2-r4
    x1 = x1 * one + (KS2 + 1u);                  // inj1: x1 += ks2+1
    RSJ(17, 1u)                                  // r5  (x0 += ks1=1, IMAD)
    RS(29)                                       // r6
    RP(0x1032u)                                  // r7  rot16
    RP(0x0321u)                                  // r8  rot24
    x1 = x1 * one + 2u;                          // inj2: x1 += ks0+2
    RSJ(13, KS2)                                 // r9  (x0 += ks2, IMAD)
    RS(15) RS(26) RS(6)                          // r10-r12
    x1 = x1 * one + 4u;                          // inj3: x1 += ks1+3
    RS(17)                                       // r13 (x0 += ks0=0, free)
    RS(29)                                       // r14
    RP(0x1032u)                                  // r15 rot16
    RP(0x0321u)                                  // r16 rot24
    x1 = x1 * one + (KS2 + 4u);                  // inj4: x1 += ks2+4
    RSJ(13, 1u)                                  // r17 (x0 += ks1=1, IMAD)
    RS(15) RS(26) RS(6)                          // r18-r20
    // final: (x0 + ks2) ^ (x1 + ks0 + 5) — both adds as IMAD
    return (x0 * one + KS2) ^ (x1 * one + 5u);
}

__global__ __launch_bounds__(256, 4)
void biased_dropout_kernel(const float4* __restrict__ x,
                           float4* __restrict__ y,
                           unsigned one) {          // always 1, opaque to ptxas
    unsigned t = blockIdx.x * blockDim.x + threadIdx.x;   // grid covers n exactly

    unsigned base = t * 8u;
    unsigned ch  = (base / HW) & 255u;               // HW % 8 == 0
    unsigned thr = (ch < 32u) ? THR_BIAS : THR_REG;

    float4 v0 = x[2u * t];
    float4 v1 = x[2u * t + 1u];

    unsigned b[8];
#pragma unroll
    for (int i = 0; i < 8; i++)
        b[i] = threefry_bits(base, (unsigned)i, one);

    float4 o0, o1;
    o0.x = (b[0] < thr) ? v0.x * 1.25f : 0.0f;
    o0.y = (b[1] < thr) ? v0.y * 1.25f : 0.0f;
    o0.z = (b[2] < thr) ? v0.z * 1.25f : 0.0f;
    o0.w = (b[3] < thr) ? v0.w * 1.25f : 0.0f;
    o1.x = (b[4] < thr) ? v1.x * 1.25f : 0.0f;
    o1.y = (b[5] < thr) ? v1.y * 1.25f : 0.0f;
    o1.z = (b[6] < thr) ? v1.z * 1.25f : 0.0f;
    o1.w = (b[7] < thr) ? v1.w * 1.25f : 0.0f;

    y[2u * t]      = o0;
    y[2u * t + 1u] = o1;
}

extern "C" void kernel_launch(void* const* d_in, const int* in_sizes, int n_in,
                              void* d_out, int out_size) {
    (void)n_in; (void)out_size;
    const float4* x = (const float4*)d_in[0];
    float4* y = (float4*)d_out;
    unsigned n = (unsigned)in_sizes[0];          // 51,380,224
    unsigned n_thr = n / 8u;                     // 6,422,528 (exact)
    unsigned blocks = n_thr / 256u;              // 25,088 (exact, no remainder)
    biased_dropout_kernel<<<blocks, 256>>>(x, y, 1u);
}

// round 16
// speedup vs baseline: 1.0258x; 1.0135x over previous
#include <cuda_runtime.h>

// BiasedFeatureDropout: out = x * 1.25 * (threefry_bits(i) < T(channel))
// Bit-exact JAX partitionable threefry-2x32, keys (0,1), counter hi=0.
//
// Round-16 build: exactly R12 (best, 134.4us) with ONE of the three
// double-IMAD x0-injections (r9, +KS2) reverted to a single 3-input
// IADD3. Model: R12 is issue-bound (instrs/0.82 = 96.7 cyc) with alu
// slack (43*2/0.94 = 91.5). k=2 trades -1 instr (issue 95.5) for +1 alu
// slot (93.6) -> new max 95.5 cyc, the family optimum.

static constexpr unsigned KS2      = 0x1BD11BDBu;   // 0 ^ 1 ^ 0x1BD11BDA
static constexpr unsigned HW       = 56u * 56u;     // 3136, divisible by 8
static constexpr unsigned THR_BIAS = 858993664u;    // keep=0.2f
static constexpr unsigned THR_REG  = 3435974144u;   // keep=0.8f

// a*one + c -> IMAD (fma pipe); 'one' is a runtime kernel arg (==1)
__device__ __forceinline__ unsigned madd(unsigned a, unsigned one, unsigned c) {
    unsigned r;
    asm("mad.lo.u32 %0, %1, %2, %3;" : "=r"(r) : "r"(a), "r"(one), "r"(c));
    return r;
}

// SHF round: IMAD add (fma) + SHF rotate (alu) + LOP3 xor (alu)
#define RS(rr)      { x0 = madd(x1, one, x0);                      \
                      x1 = __funnelshift_l(x1, x1, (rr)) ^ x0; }
// SHF round with x0 key-injection as a second IMAD (fma)
#define RSJ(rr, a)  { x0 = madd(x1, one, x0); x0 = madd(x0, one, (a)); \
                      x1 = __funnelshift_l(x1, x1, (rr)) ^ x0; }
// SHF round with x0 key-injection folded into ONE 3-input IADD3 (alu)
#define RSF(rr, a)  { x0 = x0 + x1 + (a);                          \
                      x1 = __funnelshift_l(x1, x1, (rr)) ^ x0; }
// PRMT round: rot16 sel=0x1032, rot24 sel=0x0321
#define RP(sel)     { x0 = madd(x1, one, x0);                      \
                      x1 = __byte_perm(x1, 0u, (sel)) ^ x0; }

__device__ __forceinline__ unsigned threefry_bits(unsigned base, unsigned i,
                                                  unsigned one) {
    unsigned x0, x1;
    x1 = madd(base, one, i + 1u);                // x1 = ctr + ks1(=1)
    // r1 (rot13): x0 = 0 + x1 (register alias), x1 = rot13(x1) ^ x0
    x0 = x1;
    x1 = __funnelshift_l(x1, x1, 13) ^ x0;
    RS(15) RS(26) RS(6)                          // r2-r4
    x1 = madd(x1, one, KS2 + 1u);                // inj1: x1 += ks2+1
    RSJ(17, 1u)                                  // r5  (x0 += ks1=1, IMAD)
    RS(29)                                       // r6
    RP(0x1032u)                                  // r7  rot16
    RP(0x0321u)                                  // r8  rot24
    x1 = madd(x1, one, 2u);                      // inj2: x1 += ks0+2
    RSF(13, KS2)                                 // r9  (x0 += ks2, IADD3) <- k=2
    RS(15) RS(26) RS(6)                          // r10-r12
    x1 = madd(x1, one, 4u);                      // inj3: x1 += ks1+3
    RS(17)                                       // r13 (x0 += ks0=0, free)
    RS(29)                                       // r14
    RP(0x1032u)                                  // r15 rot16
    RP(0x0321u)                                  // r16 rot24
    x1 = madd(x1, one, KS2 + 4u);                // inj4: x1 += ks2+4
    RSJ(13, 1u)                                  // r17 (x0 += ks1=1, IMAD)
    RS(15) RS(26) RS(6)                          // r18-r20
    // final: (x0 + ks2) ^ (x1 + ks0 + 5) — both adds on IMAD
    return madd(x0, one, KS2) ^ madd(x1, one, 5u);
}

__global__ __launch_bounds__(256, 4)
void biased_dropout_kernel(const float4* __restrict__ x,
                           float4* __restrict__ y,
                           unsigned one) {          // always 1, opaque to ptxas
    unsigned t = blockIdx.x * blockDim.x + threadIdx.x;   // grid covers n exactly

    unsigned base = t * 8u;
    unsigned ch  = (base / HW) & 255u;               // HW % 8 == 0
    unsigned thr = (ch < 32u) ? THR_BIAS : THR_REG;

    float4 v0 = x[2u * t];
    float4 v1 = x[2u * t + 1u];

    unsigned b[8];
#pragma unroll
    for (int i = 0; i < 8; i++)
        b[i] = threefry_bits(base, (unsigned)i, one);

    float4 o0, o1;
    o0.x = (b[0] < thr) ? v0.x * 1.25f : 0.0f;
    o0.y = (b[1] < thr) ? v0.y * 1.25f : 0.0f;
    o0.z = (b[2] < thr) ? v0.z * 1.25f : 0.0f;
    o0.w = (b[3] < thr) ? v0.w * 1.25f : 0.0f;
    o1.x = (b[4] < thr) ? v1.x * 1.25f : 0.0f;
    o1.y = (b[5] < thr) ? v1.y * 1.25f : 0.0f;
    o1.z = (b[6] < thr) ? v1.z * 1.25f : 0.0f;
    o1.w = (b[7] < thr) ? v1.w * 1.25f : 0.0f;

    y[2u * t]      = o0;
    y[2u * t + 1u] = o1;
}

extern "C" void kernel_launch(void* const* d_in, const int* in_sizes, int n_in,
                              void* d_out, int out_size) {
    (void)n_in; (void)out_size;
    const float4* x = (const float4*)d_in[0];
    float4* y = (float4*)d_out;
    unsigned n = (unsigned)in_sizes[0];          // 51,380,224
    unsigned n_thr = n / 8u;                     // 6,422,528 (exact)
    unsigned blocks = n_thr / 256u;              // 25,088 (exact, no remainder)
    biased_dropout_kernel<<<blocks, 256>>>(x, y, 1u);
}

// round 17
// speedup vs baseline: 1.0408x; 1.0146x over previous
#include <cuda_runtime.h>

// BiasedFeatureDropout: out = x * 1.25 * (threefry_bits(i) < T(channel))
// Bit-exact JAX partitionable threefry-2x32, keys (0,1), counter hi=0.
//
// FINAL (= R12, best measured 134.4us): all adds steered to the fma pipe
// as IMAD via runtime-opaque 'one' (incl. the 3 x0-injections as double
// IMADs), rot16/rot24 via PRMT, remaining 16 rotates via SHF, integer
// threshold compare (float RNG math folded away analytically).
// Measured: alu 90.9% (0.455/0.5 binding), combined int issue 0.82
// (chip ceiling for this dependency structure), occ 94%, regs 32.

static constexpr unsigned KS2      = 0x1BD11BDBu;   // 0 ^ 1 ^ 0x1BD11BDA
static constexpr unsigned HW       = 56u * 56u;     // 3136, divisible by 8
static constexpr unsigned THR_BIAS = 858993664u;    // keep=0.2f
static constexpr unsigned THR_REG  = 3435974144u;   // keep=0.8f

// a*one + c -> IMAD (fma pipe); 'one' is a runtime kernel arg (==1)
__device__ __forceinline__ unsigned madd(unsigned a, unsigned one, unsigned c) {
    unsigned r;
    asm("mad.lo.u32 %0, %1, %2, %3;" : "=r"(r) : "r"(a), "r"(one), "r"(c));
    return r;
}

// SHF round: IMAD add (fma) + SHF rotate (alu) + LOP3 xor (alu)
#define RS(rr)      { x0 = madd(x1, one, x0);                      \
                      x1 = __funnelshift_l(x1, x1, (rr)) ^ x0; }
// SHF round with x0 key-injection as a second IMAD (fma)
#define RSJ(rr, a)  { x0 = madd(x1, one, x0); x0 = madd(x0, one, (a)); \
                      x1 = __funnelshift_l(x1, x1, (rr)) ^ x0; }
// PRMT round: rot16 sel=0x1032, rot24 sel=0x0321
#define RP(sel)     { x0 = madd(x1, one, x0);                      \
                      x1 = __byte_perm(x1, 0u, (sel)) ^ x0; }

__device__ __forceinline__ unsigned threefry_bits(unsigned base, unsigned i,
                                                  unsigned one) {
    unsigned x0, x1;
    x1 = madd(base, one, i + 1u);                // x1 = ctr + ks1(=1)
    // r1 (rot13): x0 = 0 + x1 (register alias), x1 = rot13(x1) ^ x0
    x0 = x1;
    x1 = __funnelshift_l(x1, x1, 13) ^ x0;
    RS(15) RS(26) RS(6)                          // r2-r4
    x1 = madd(x1, one, KS2 + 1u);                // inj1: x1 += ks2+1
    RSJ(17, 1u)                                  // r5  (x0 += ks1=1, IMAD)
    RS(29)                                       // r6
    RP(0x1032u)                                  // r7  rot16
    RP(0x0321u)                                  // r8  rot24
    x1 = madd(x1, one, 2u);                      // inj2: x1 += ks0+2
    RSJ(13, KS2)                                 // r9  (x0 += ks2, IMAD)
    RS(15) RS(26) RS(6)                          // r10-r12
    x1 = madd(x1, one, 4u);                      // inj3: x1 += ks1+3
    RS(17)                                       // r13 (x0 += ks0=0, free)
    RS(29)                                       // r14
    RP(0x1032u)                                  // r15 rot16
    RP(0x0321u)                                  // r16 rot24
    x1 = madd(x1, one, KS2 + 4u);                // inj4: x1 += ks2+4
    RSJ(13, 1u)                                  // r17 (x0 += ks1=1, IMAD)
    RS(15) RS(26) RS(6)                          // r18-r20
    // final: (x0 + ks2) ^ (x1 + ks0 + 5) — both adds on IMAD
    return madd(x0, one, KS2) ^ madd(x1, one, 5u);
}

__global__ __launch_bounds__(256, 4)
void biased_dropout_kernel(const float4* __restrict__ x,
                           float4* __restrict__ y,
                           unsigned one) {          // always 1, opaque to ptxas
    unsigned t = blockIdx.x * blockDim.x + threadIdx.x;   // grid covers n exactly

    unsigned base = t * 8u;
    unsigned ch  = (base / HW) & 255u;               // HW % 8 == 0
    unsigned thr = (ch < 32u) ? THR_BIAS : THR_REG;

    float4 v0 = x[2u * t];
    float4 v1 = x[2u * t + 1u];

    unsigned b[8];
#pragma unroll
    for (int i = 0; i < 8; i++)
        b[i] = threefry_bits(base, (unsigned)i, one);

    float4 o0, o1;
    o0.x = (b[0] < thr) ? v0.x * 1.25f : 0.0f;
    o0.y = (b[1] < thr) ? v0.y * 1.25f : 0.0f;
    o0.z = (b[2] < thr) ? v0.z * 1.25f : 0.0f;
    o0.w = (b[3] < thr) ? v0.w * 1.25f : 0.0f;
    o1.x = (b[4] < thr) ? v1.x * 1.25f : 0.0f;
    o1.y = (b[5] < thr) ? v1.y * 1.25f : 0.0f;
    o1.z = (b[6] < thr) ? v1.z * 1.25f : 0.0f;
    o1.w = (b[7] < thr) ? v1.w * 1.25f : 0.0f;

    y[2u * t]      = o0;
    y[2u * t + 1u] = o1;
}

extern "C" void kernel_launch(void* const* d_in, const int* in_sizes, int n_in,
                              void* d_out, int out_size) {
    (void)n_in; (void)out_size;
    const float4* x = (const float4*)d_in[0];
    float4* y = (float4*)d_out;
    unsigned n = (unsigned)in_sizes[0];          // 51,380,224
    unsigned n_thr = n / 8u;                     // 6,422,528 (exact)
    unsigned blocks = n_thr / 256u;              // 25,088 (exact, no remainder)
    biased_dropout_kernel<<<blocks, 256>>>(x, y, 1u);
}